// round 3
// baseline (speedup 1.0000x reference)
#include <cuda_runtime.h>
#include <cuda_bf16.h>
#include <cstdint>

// Problem constants
#define GB 4
#define GL 4096
#define GD 2048
#define GN_STATE 16
#define GM (GB*GL)          // 16384 rows
#define GK GD               // 2048
#define GN GD               // 2048
#define DT_MIN 1e-4f

#define PLANE ((size_t)GM * GD)   // elements per projection plane

// Single scratch symbol: plane 0 = dt, plane 1 = b, plane 2 = c
__device__ float g_proj[3 * PLANE];

__device__ __forceinline__ float tf32r(float x) {
    uint32_t o;
    asm("cvt.rna.tf32.f32 %0, %1;" : "=r"(o) : "f"(x));
    return __uint_as_float(o);
}

__device__ __forceinline__ float softplus_f(float x) {
    return log1pf(expf(-fabsf(x))) + fmaxf(x, 0.0f);
}

__device__ __forceinline__ void mma_tf32(float c[4], const uint32_t a[4],
                                         uint32_t b0, uint32_t b1) {
    asm volatile(
        "mma.sync.aligned.m16n8k8.row.col.f32.tf32.tf32.f32 "
        "{%0,%1,%2,%3}, {%4,%5,%6,%7}, {%8,%9}, {%0,%1,%2,%3};\n"
        : "+f"(c[0]), "+f"(c[1]), "+f"(c[2]), "+f"(c[3])
        : "r"(a[0]), "r"(a[1]), "r"(a[2]), "r"(a[3]), "r"(b0), "r"(b1));
}

// ---------------------------------------------------------------------------
// GEMM: out(z) = u @ W(z) + bias(z); z=0 -> dt (softplus epilogue), 1 -> b, 2 -> c
// Block tile 128x128, K-step 32, 256 threads = 8 warps (4 along M, 2 along N),
// warp tile 32x64 -> 2x8 m16n8k8 tf32 mma tiles.
// ---------------------------------------------------------------------------
__global__ void __launch_bounds__(256, 2)
gemm3_kernel(const float* __restrict__ u,
             const float* __restrict__ Wdt, const float* __restrict__ bdt,
             const float* __restrict__ Wb,  const float* __restrict__ bb,
             const float* __restrict__ Wc,  const float* __restrict__ bc) {
    __shared__ float sA[128][36];   // [m][k], stride 36 -> conflict-free frag reads
    __shared__ float sB[32][132];   // [k][n], stride 132 -> conflict-free frag reads

    const int z = blockIdx.z;
    const float* __restrict__ W    = (z == 0) ? Wdt : ((z == 1) ? Wb : Wc);
    const float* __restrict__ bias = (z == 0) ? bdt : ((z == 1) ? bb : bc);
    float* __restrict__ out        = g_proj + (size_t)z * PLANE;

    const int bm = blockIdx.y * 128;
    const int bn = blockIdx.x * 128;
    const int tid  = threadIdx.x;
    const int lane = tid & 31;
    const int warp = tid >> 5;
    const int wm = (warp & 3) * 32;   // warp M offset (4 warps)
    const int wn = (warp >> 2) * 64;  // warp N offset (2 warps)
    const int g  = lane >> 2;         // groupID 0..7
    const int th = lane & 3;          // thread-in-group 0..3

    float acc[2][8][4];
    #pragma unroll
    for (int i = 0; i < 2; i++)
        #pragma unroll
        for (int j = 0; j < 8; j++)
            #pragma unroll
            for (int k = 0; k < 4; k++) acc[i][j][k] = 0.0f;

    for (int k0 = 0; k0 < GK; k0 += 32) {
        // load A tile: 128x32, 1024 float4 by 256 threads (4 each)
        #pragma unroll
        for (int i = 0; i < 4; i++) {
            int lin = tid + i * 256;
            int row = lin >> 3;
            int c4  = (lin & 7) << 2;
            const float4 v = *reinterpret_cast<const float4*>(
                u + (size_t)(bm + row) * GK + k0 + c4);
            sA[row][c4 + 0] = tf32r(v.x);
            sA[row][c4 + 1] = tf32r(v.y);
            sA[row][c4 + 2] = tf32r(v.z);
            sA[row][c4 + 3] = tf32r(v.w);
        }
        // load B tile: 32x128
        #pragma unroll
        for (int i = 0; i < 4; i++) {
            int lin = tid + i * 256;
            int kr = lin >> 5;
            int n4 = (lin & 31) << 2;
            const float4 v = *reinterpret_cast<const float4*>(
                W + (size_t)(k0 + kr) * GN + bn + n4);
            sB[kr][n4 + 0] = tf32r(v.x);
            sB[kr][n4 + 1] = tf32r(v.y);
            sB[kr][n4 + 2] = tf32r(v.z);
            sB[kr][n4 + 3] = tf32r(v.w);
        }
        __syncthreads();

        #pragma unroll
        for (int kk = 0; kk < 4; kk++) {
            uint32_t a[2][4];
            #pragma unroll
            for (int mt = 0; mt < 2; mt++) {
                int r = wm + mt * 16 + g;
                a[mt][0] = __float_as_uint(sA[r    ][kk * 8 + th    ]);
                a[mt][1] = __float_as_uint(sA[r + 8][kk * 8 + th    ]);
                a[mt][2] = __float_as_uint(sA[r    ][kk * 8 + th + 4]);
                a[mt][3] = __float_as_uint(sA[r + 8][kk * 8 + th + 4]);
            }
            #pragma unroll
            for (int nt = 0; nt < 8; nt++) {
                uint32_t b0 = __float_as_uint(sB[kk * 8 + th    ][wn + nt * 8 + g]);
                uint32_t b1 = __float_as_uint(sB[kk * 8 + th + 4][wn + nt * 8 + g]);
                mma_tf32(acc[0][nt], a[0], b0, b1);
                mma_tf32(acc[1][nt], a[1], b0, b1);
            }
        }
        __syncthreads();
    }

    // epilogue
    #pragma unroll
    for (int mt = 0; mt < 2; mt++) {
        #pragma unroll
        for (int nt = 0; nt < 8; nt++) {
            int r0 = bm + wm + mt * 16 + g;
            int c0 = bn + wn + nt * 8 + 2 * th;
            #pragma unroll
            for (int e = 0; e < 4; e++) {
                int r = r0 + ((e >> 1) << 3);   // +8 for e=2,3
                int c = c0 + (e & 1);
                float v = acc[mt][nt][e] + bias[c];
                if (z == 0) v = softplus_f(v) + DT_MIN;
                out[(size_t)r * GN + c] = v;
            }
        }
    }
}

// ---------------------------------------------------------------------------
// Selective scan: one lane per (channel, n); 16 lanes per channel, 2 channels
// per warp, 16 channels per 256-thread block, 512 blocks total.
// ---------------------------------------------------------------------------
__global__ void __launch_bounds__(256)
scan_kernel(const float* __restrict__ u,
            const float* __restrict__ a_raw,
            const float* __restrict__ B_base,
            const float* __restrict__ C_base,
            const float* __restrict__ Dv,
            float* __restrict__ carry,   // may be nullptr
            float* __restrict__ y) {
    const int n   = threadIdx.x & 15;
    const int lch = threadIdx.x >> 4;
    const int ch  = blockIdx.x * 16 + lch;
    const int b = ch >> 11;       // /2048
    const int d = ch & 2047;

    const float A  = -softplus_f(a_raw[d * GN_STATE + n]);
    const float kA = A * 1.4426950408889634f;   // for exp2
    const float Bb = B_base[d * GN_STATE + n];
    const float Cb = C_base[d * GN_STATE + n];
    const float Dd = Dv[d];

    size_t idx = (size_t)b * GL * GD + d;
    const float* __restrict__ pdt = g_proj;              // plane 0
    const float* __restrict__ pb  = g_proj + PLANE;      // plane 1
    const float* __restrict__ pc  = g_proj + 2 * PLANE;  // plane 2
    float x = 0.0f;

    #pragma unroll 8
    for (int t = 0; t < GL; t++) {
        const float us  = __ldg(u + idx);
        const float dts = pdt[idx];
        const float bs  = pb[idx];
        const float cs  = pc[idx];
        float Abar;
        asm("ex2.approx.ftz.f32 %0, %1;" : "=f"(Abar) : "f"(dts * kA));
        x = fmaf(Abar, x, (dts * bs * Bb) * us);
        float p = cs * Cb * x;
        p += __shfl_xor_sync(0xffffffffu, p, 8);
        p += __shfl_xor_sync(0xffffffffu, p, 4);
        p += __shfl_xor_sync(0xffffffffu, p, 2);
        p += __shfl_xor_sync(0xffffffffu, p, 1);
        if (n == 0) y[idx] = p + Dd * us;
        idx += GD;
    }

    if (carry != nullptr)
        carry[((size_t)b * GD + d) * GN_STATE + n] = x;
}

extern "C" void kernel_launch(void* const* d_in, const int* in_sizes, int n_in,
                              void* d_out, int out_size) {
    const float* u      = (const float*)d_in[0];
    const float* Wdt    = (const float*)d_in[1];
    const float* bdt    = (const float*)d_in[2];
    const float* Wb     = (const float*)d_in[3];
    const float* bb     = (const float*)d_in[4];
    const float* Wc     = (const float*)d_in[5];
    const float* bc     = (const float*)d_in[6];
    const float* a_raw  = (const float*)d_in[7];
    const float* B_base = (const float*)d_in[8];
    const float* C_base = (const float*)d_in[9];
    const float* Dv     = (const float*)d_in[10];

    float* out = (float*)d_out;
    const long long y_elems = (long long)GB * GL * GD;   // 33,554,432
    float* carry = nullptr;
    float* y = out;
    if ((long long)out_size > y_elems) {
        // output = concat(flatten(carry_out), flatten(y))
        carry = out;
        y = out + ((long long)out_size - y_elems);
    }

    dim3 gemm_grid(GN / 128, GM / 128, 3);   // (16, 128, 3)
    gemm3_kernel<<<gemm_grid, 256>>>(u, Wdt, bdt, Wb, bb, Wc, bc);

    scan_kernel<<<GB * GD / 16, 256>>>(u, a_raw, B_base, C_base, Dv, carry, y);
}

// round 6
// speedup vs baseline: 1.5106x; 1.5106x over previous
#include <cuda_runtime.h>
#include <cstdint>

// ---------------------------------------------------------------------------
// Problem constants
// ---------------------------------------------------------------------------
#define GB 4
#define GL 4096
#define GD 2048
#define GN_STATE 16
#define GM (GB*GL)          // 16384
#define GK GD               // 2048
#define DT_MIN 1e-4f
#define PLANE ((size_t)GM * GD)

// Projections stored TRANSPOSED: [z][d][m]
__device__ float g_proj[3 * PLANE];
// Transposed tf32-rounded weights: [z][d][k]
__device__ float g_wt[(size_t)3 * GD * GK];
// tf32-rounded u, GEMM orientation [m][k]
__device__ float g_up[PLANE];
// tf32-rounded u, scan orientation [d][m]
__device__ float g_ut[PLANE];

__device__ __forceinline__ uint32_t smem_u32(const void* p) {
    uint32_t a;
    asm("{ .reg .u64 t; cvta.to.shared.u64 t, %1; cvt.u32.u64 %0, t; }" : "=r"(a) : "l"(p));
    return a;
}
__device__ __forceinline__ uint32_t tf32u(float x) {
    uint32_t o;
    asm("cvt.rna.tf32.f32 %0, %1;" : "=r"(o) : "f"(x));
    return o;
}
__device__ __forceinline__ float softplus_f(float x) {
    return log1pf(expf(-fabsf(x))) + fmaxf(x, 0.0f);
}
__device__ __forceinline__ void mma_tf32(float c[4], const uint32_t a[4],
                                         uint32_t b0, uint32_t b1) {
    asm volatile(
        "mma.sync.aligned.m16n8k8.row.col.f32.tf32.tf32.f32 "
        "{%0,%1,%2,%3}, {%4,%5,%6,%7}, {%8,%9}, {%0,%1,%2,%3};\n"
        : "+f"(c[0]), "+f"(c[1]), "+f"(c[2]), "+f"(c[3])
        : "r"(a[0]), "r"(a[1]), "r"(a[2]), "r"(a[3]), "r"(b0), "r"(b1));
}
__device__ __forceinline__ void cp_async16(uint32_t dst, const void* src) {
    asm volatile("cp.async.cg.shared.global [%0], [%1], 16;" :: "r"(dst), "l"(src));
}

// ---------------------------------------------------------------------------
// Prep: weight transpose + tf32 round. g_wt[z][d][k] = tf32(W_z[k][d])
// ---------------------------------------------------------------------------
__global__ void wtrans_kernel(const float* __restrict__ Wdt,
                              const float* __restrict__ Wb,
                              const float* __restrict__ Wc) {
    __shared__ float t[32][33];
    const int z = blockIdx.z;
    const float* __restrict__ W = (z == 0) ? Wdt : ((z == 1) ? Wb : Wc);
    float* __restrict__ out = g_wt + (size_t)z * GD * GK;
    const int k0 = blockIdx.x * 32, d0 = blockIdx.y * 32;
    for (int i = threadIdx.y; i < 32; i += 8)
        t[i][threadIdx.x] = W[(size_t)(k0 + i) * GD + d0 + threadIdx.x];
    __syncthreads();
    for (int i = threadIdx.y; i < 32; i += 8)
        out[(size_t)(d0 + i) * GK + k0 + threadIdx.x] =
            __uint_as_float(tf32u(t[threadIdx.x][i]));
}

// ---------------------------------------------------------------------------
// Prep: u -> tf32-rounded copies. g_up[m][d]=tf32(u), g_ut[d][m]=tf32(u)
// ---------------------------------------------------------------------------
__global__ void uprep_kernel(const float* __restrict__ u) {
    __shared__ float t[32][33];
    const int d0 = blockIdx.x * 32, m0 = blockIdx.y * 32;
    for (int i = threadIdx.y; i < 32; i += 8) {
        float v = u[(size_t)(m0 + i) * GD + d0 + threadIdx.x];
        float r = __uint_as_float(tf32u(v));
        t[i][threadIdx.x] = r;
        g_up[(size_t)(m0 + i) * GD + d0 + threadIdx.x] = r;
    }
    __syncthreads();
    for (int i = threadIdx.y; i < 32; i += 8)
        g_ut[(size_t)(d0 + i) * GM + m0 + threadIdx.x] = t[threadIdx.x][i];
}

// ---------------------------------------------------------------------------
// Pipelined tf32 GEMM: out_t[z][d][m] = sum_k Wt[z][d][k]*u[m][k] (+bias,+sp)
// Block tile 128(d=M) x 256(m=N), 512 threads (16 warps: 4 M x 4 N),
// warp tile 32x64, K-chunk 32, cp.async 2-stage double buffer.
// Smem pitch 36 floats -> conflict-free fragment reads (bank = 4g+th = lane).
// ---------------------------------------------------------------------------
#define KCH 32
#define PITCH 36
#define A_STAGE (128 * PITCH * 4)   // 18432 B
#define B_STAGE (256 * PITCH * 4)   // 36864 B
#define GEMM_SMEM (2 * A_STAGE + 2 * B_STAGE)   // 110592 B
#define NCH (GK / KCH)              // 64

__global__ void __launch_bounds__(512, 1)
gemm_tc_kernel(const float* __restrict__ bdt, const float* __restrict__ bb,
               const float* __restrict__ bc) {
    extern __shared__ float smem[];
    float* sA[2] = { smem, smem + 128 * PITCH };
    float* sB[2] = { smem + 2 * 128 * PITCH, smem + 2 * 128 * PITCH + 256 * PITCH };

    const int tid = threadIdx.x;
    const int lane = tid & 31;
    const int warp = tid >> 5;
    const int z    = blockIdx.x >> 4;          // 0..2
    const int bd   = (blockIdx.x & 15) * 128;  // d block
    const int bm   = blockIdx.y * 256;         // m block
    const float* __restrict__ W = g_wt + (size_t)z * GD * GK;
    const float* __restrict__ bias = (z == 0) ? bdt : ((z == 1) ? bb : bc);
    float* __restrict__ out = g_proj + (size_t)z * PLANE;

    const int wm = (warp & 3) * 32;     // warp d offset
    const int wn = (warp >> 2) * 64;    // warp m offset
    const int g  = lane >> 2;
    const int th = lane & 3;

    // cp.async loader for one stage
    auto load_stage = [&](int c, int buf) {
        const int k0 = c * KCH;
        const uint32_t aB = smem_u32(sA[buf]);
        const uint32_t bB = smem_u32(sB[buf]);
        // A: 128 rows x 8 16B-chunks = 1024 -> 2 per thread
        #pragma unroll
        for (int i = 0; i < 2; i++) {
            int lin = tid + i * 512;
            int row = lin >> 3, ch = lin & 7;
            cp_async16(aB + (row * PITCH + ch * 4) * 4,
                       W + (size_t)(bd + row) * GK + k0 + ch * 4);
        }
        // B: 256 rows x 8 chunks = 2048 -> 4 per thread
        #pragma unroll
        for (int i = 0; i < 4; i++) {
            int lin = tid + i * 512;
            int row = lin >> 3, ch = lin & 7;
            cp_async16(bB + (row * PITCH + ch * 4) * 4,
                       g_up + (size_t)(bm + row) * GK + k0 + ch * 4);
        }
        asm volatile("cp.async.commit_group;" ::: "memory");
    };

    float acc[2][8][4];
    #pragma unroll
    for (int i = 0; i < 2; i++)
        #pragma unroll
        for (int j = 0; j < 8; j++)
            #pragma unroll
            for (int k = 0; k < 4; k++) acc[i][j][k] = 0.0f;

    load_stage(0, 0);
    load_stage(1, 1);

    for (int c = 0; c < NCH; c++) {
        const int buf = c & 1;
        if (c == NCH - 1)
            asm volatile("cp.async.wait_group 0;" ::: "memory");
        else
            asm volatile("cp.async.wait_group 1;" ::: "memory");
        __syncthreads();

        const float* a_base = sA[buf];
        const float* b_base = sB[buf];
        #pragma unroll
        for (int kk = 0; kk < 4; kk++) {
            uint32_t a[2][4];
            #pragma unroll
            for (int mt = 0; mt < 2; mt++) {
                int r = wm + mt * 16 + g;
                const float* ap = a_base + r * PITCH + kk * 8 + th;
                a[mt][0] = __float_as_uint(ap[0]);
                a[mt][1] = __float_as_uint(ap[8 * PITCH]);
                a[mt][2] = __float_as_uint(ap[4]);
                a[mt][3] = __float_as_uint(ap[8 * PITCH + 4]);
            }
            #pragma unroll
            for (int nt = 0; nt < 8; nt++) {
                const float* bp = b_base + (wn + nt * 8 + g) * PITCH + kk * 8 + th;
                uint32_t b0 = __float_as_uint(bp[0]);
                uint32_t b1 = __float_as_uint(bp[4]);
                mma_tf32(acc[0][nt], a[0], b0, b1);
                mma_tf32(acc[1][nt], a[1], b0, b1);
            }
        }
        __syncthreads();
        if (c + 2 < NCH) load_stage(c + 2, buf);
    }

    // Epilogue: out[d][m] (m contiguous)
    #pragma unroll
    for (int mt = 0; mt < 2; mt++) {
        #pragma unroll
        for (int e2 = 0; e2 < 2; e2++) {      // row halves (+0 / +8)
            int r = bd + wm + mt * 16 + g + e2 * 8;
            float bv = bias[r];
            float* orow = out + (size_t)r * GM + bm;
            #pragma unroll
            for (int nt = 0; nt < 8; nt++) {
                int c0 = wn + nt * 8 + 2 * th;
                float2 v;
                v.x = acc[mt][nt][e2 * 2 + 0] + bv;
                v.y = acc[mt][nt][e2 * 2 + 1] + bv;
                if (z == 0) {
                    v.x = softplus_f(v.x) + DT_MIN;
                    v.y = softplus_f(v.y) + DT_MIN;
                }
                *reinterpret_cast<float2*>(orow + c0) = v;
            }
        }
    }
}

// ---------------------------------------------------------------------------
// Selective scan: lane per (channel, n); all 4 input streams contiguous.
// ---------------------------------------------------------------------------
__global__ void __launch_bounds__(256)
scan_kernel(const float* __restrict__ a_raw,
            const float* __restrict__ B_base,
            const float* __restrict__ C_base,
            const float* __restrict__ Dv,
            float* __restrict__ carry, float* __restrict__ y) {
    const int n = threadIdx.x & 15;
    const int lch = threadIdx.x >> 4;
    const int ch = blockIdx.x * 16 + lch;
    const int b = ch >> 11;
    const int d = ch & 2047;

    const float A  = -softplus_f(a_raw[d * GN_STATE + n]);
    const float kA = A * 1.4426950408889634f;
    const float Bb = B_base[d * GN_STATE + n];
    const float Cb = C_base[d * GN_STATE + n];
    const float Dd = Dv[d];

    const size_t sbase = (size_t)d * GM + (size_t)b * GL;
    const float* __restrict__ pu  = g_ut + sbase;
    const float* __restrict__ pdt = g_proj + sbase;
    const float* __restrict__ pbv = g_proj + PLANE + sbase;
    const float* __restrict__ pcv = g_proj + 2 * PLANE + sbase;
    size_t yidx = (size_t)b * GL * GD + d;
    float x = 0.0f;

    #pragma unroll 8
    for (int t = 0; t < GL; t++) {
        const float us  = pu[t];
        const float dts = pdt[t];
        const float bs  = pbv[t];
        const float cs  = pcv[t];
        float Abar;
        asm("ex2.approx.ftz.f32 %0, %1;" : "=f"(Abar) : "f"(dts * kA));
        x = fmaf(Abar, x, (dts * bs * Bb) * us);
        float p = cs * Cb * x;
        p += __shfl_xor_sync(0xffffffffu, p, 8);
        p += __shfl_xor_sync(0xffffffffu, p, 4);
        p += __shfl_xor_sync(0xffffffffu, p, 2);
        p += __shfl_xor_sync(0xffffffffu, p, 1);
        if (n == 0) y[yidx] = p + Dd * us;
        yidx += GD;
    }

    if (carry != nullptr)
        carry[((size_t)b * GD + d) * GN_STATE + n] = x;
}

// ---------------------------------------------------------------------------
extern "C" void kernel_launch(void* const* d_in, const int* in_sizes, int n_in,
                              void* d_out, int out_size) {
    const float* u      = (const float*)d_in[0];
    const float* Wdt    = (const float*)d_in[1];
    const float* bdt    = (const float*)d_in[2];
    const float* Wb     = (const float*)d_in[3];
    const float* bb     = (const float*)d_in[4];
    const float* Wc     = (const float*)d_in[5];
    const float* bc     = (const float*)d_in[6];
    const float* a_raw  = (const float*)d_in[7];
    const float* B_base = (const float*)d_in[8];
    const float* C_base = (const float*)d_in[9];
    const float* Dv     = (const float*)d_in[10];

    float* out = (float*)d_out;
    const long long y_elems = (long long)GB * GL * GD;
    float* carry = nullptr;
    float* y = out;
    if ((long long)out_size > y_elems) {
        carry = out;
        y = out + ((long long)out_size - y_elems);
    }

    cudaFuncSetAttribute(gemm_tc_kernel,
                         cudaFuncAttributeMaxDynamicSharedMemorySize, GEMM_SMEM);

    dim3 tgrid(GK / 32, GD / 32, 3);
    wtrans_kernel<<<tgrid, dim3(32, 8)>>>(Wdt, Wb, Wc);

    dim3 ugrid(GD / 32, GM / 32);
    uprep_kernel<<<ugrid, dim3(32, 8)>>>(u);

    dim3 ggrid(3 * (GD / 128), GM / 256);   // (48, 64)
    gemm_tc_kernel<<<ggrid, 512, GEMM_SMEM>>>(bdt, bb, bc);

    scan_kernel<<<GB * GD / 16, 256>>>(a_raw, B_base, C_base, Dv, carry, y);
}

// round 7
// speedup vs baseline: 2.0390x; 1.3498x over previous
#include <cuda_runtime.h>
#include <cstdint>

// ---------------------------------------------------------------------------
// Problem constants
// ---------------------------------------------------------------------------
#define GB 4
#define GL 4096
#define GD 2048
#define GN_STATE 16
#define GM (GB*GL)          // 16384
#define GK GD               // 2048
#define DT_MIN 1e-4f
#define PLANE ((size_t)GM * GD)
#define NCHAN (GB * GD)     // 8192 channels
#define CCH 16              // scan chunks
#define TCH (GL / CCH)      // 256 steps per chunk

// Projections stored TRANSPOSED: [z][d][m]
__device__ float g_proj[3 * PLANE];
// Transposed tf32-rounded weights: [z][d][k]
__device__ float g_wt[(size_t)3 * GD * GK];
// tf32-rounded u, GEMM orientation [m][k]
__device__ float g_up[PLANE];
// tf32-rounded u, scan orientation [d][m]
__device__ float g_ut[PLANE];
// Scan chunk carries
__device__ float g_P [(CCH - 1) * NCHAN * GN_STATE];
__device__ float g_S [(CCH - 1) * NCHAN * GN_STATE];
__device__ float g_x0[CCH * NCHAN * GN_STATE];

__device__ __forceinline__ uint32_t smem_u32(const void* p) {
    uint32_t a;
    asm("{ .reg .u64 t; cvta.to.shared.u64 t, %1; cvt.u32.u64 %0, t; }" : "=r"(a) : "l"(p));
    return a;
}
__device__ __forceinline__ uint32_t tf32u(float x) {
    uint32_t o;
    asm("cvt.rna.tf32.f32 %0, %1;" : "=r"(o) : "f"(x));
    return o;
}
__device__ __forceinline__ float softplus_f(float x) {
    return log1pf(expf(-fabsf(x))) + fmaxf(x, 0.0f);
}
__device__ __forceinline__ float ex2f(float x) {
    float r;
    asm("ex2.approx.ftz.f32 %0, %1;" : "=f"(r) : "f"(x));
    return r;
}
__device__ __forceinline__ void mma_tf32(float c[4], const uint32_t a[4],
                                         uint32_t b0, uint32_t b1) {
    asm volatile(
        "mma.sync.aligned.m16n8k8.row.col.f32.tf32.tf32.f32 "
        "{%0,%1,%2,%3}, {%4,%5,%6,%7}, {%8,%9}, {%0,%1,%2,%3};\n"
        : "+f"(c[0]), "+f"(c[1]), "+f"(c[2]), "+f"(c[3])
        : "r"(a[0]), "r"(a[1]), "r"(a[2]), "r"(a[3]), "r"(b0), "r"(b1));
}
__device__ __forceinline__ void cp_async16(uint32_t dst, const void* src) {
    asm volatile("cp.async.cg.shared.global [%0], [%1], 16;" :: "r"(dst), "l"(src));
}

// ---------------------------------------------------------------------------
// Prep kernels
// ---------------------------------------------------------------------------
__global__ void wtrans_kernel(const float* __restrict__ Wdt,
                              const float* __restrict__ Wb,
                              const float* __restrict__ Wc) {
    __shared__ float t[32][33];
    const int z = blockIdx.z;
    const float* __restrict__ W = (z == 0) ? Wdt : ((z == 1) ? Wb : Wc);
    float* __restrict__ out = g_wt + (size_t)z * GD * GK;
    const int k0 = blockIdx.x * 32, d0 = blockIdx.y * 32;
    for (int i = threadIdx.y; i < 32; i += 8)
        t[i][threadIdx.x] = W[(size_t)(k0 + i) * GD + d0 + threadIdx.x];
    __syncthreads();
    for (int i = threadIdx.y; i < 32; i += 8)
        out[(size_t)(d0 + i) * GK + k0 + threadIdx.x] =
            __uint_as_float(tf32u(t[threadIdx.x][i]));
}

__global__ void uprep_kernel(const float* __restrict__ u) {
    __shared__ float t[32][33];
    const int d0 = blockIdx.x * 32, m0 = blockIdx.y * 32;
    for (int i = threadIdx.y; i < 32; i += 8) {
        float v = u[(size_t)(m0 + i) * GD + d0 + threadIdx.x];
        float r = __uint_as_float(tf32u(v));
        t[i][threadIdx.x] = r;
        g_up[(size_t)(m0 + i) * GD + d0 + threadIdx.x] = r;
    }
    __syncthreads();
    for (int i = threadIdx.y; i < 32; i += 8)
        g_ut[(size_t)(d0 + i) * GM + m0 + threadIdx.x] = t[threadIdx.x][i];
}

// ---------------------------------------------------------------------------
// Pipelined tf32 GEMM (3-stage cp.async, one sync per K-iter)
// Block 128(d=M) x 256(m=N), 512 threads, warp tile 32x64, K-chunk 32.
// ---------------------------------------------------------------------------
#define KCH 32
#define PITCH 36
#define A_FLOATS (128 * PITCH)
#define B_FLOATS (256 * PITCH)
#define STAGE_FLOATS (A_FLOATS + B_FLOATS)
#define GEMM_SMEM (3 * STAGE_FLOATS * 4)   // 165888 B
#define NCH (GK / KCH)              // 64

__global__ void __launch_bounds__(512, 1)
gemm_tc_kernel(const float* __restrict__ bdt, const float* __restrict__ bb,
               const float* __restrict__ bc) {
    extern __shared__ float smem[];

    const int tid = threadIdx.x;
    const int lane = tid & 31;
    const int warp = tid >> 5;
    const int z    = blockIdx.x >> 4;
    const int bd   = (blockIdx.x & 15) * 128;
    const int bm   = blockIdx.y * 256;
    const float* __restrict__ W = g_wt + (size_t)z * GD * GK;
    const float* __restrict__ bias = (z == 0) ? bdt : ((z == 1) ? bb : bc);
    float* __restrict__ out = g_proj + (size_t)z * PLANE;

    const int wm = (warp & 3) * 32;
    const int wn = (warp >> 2) * 64;
    const int g  = lane >> 2;
    const int th = lane & 3;

    auto load_stage = [&](int c, int buf) {
        const int k0 = c * KCH;
        const uint32_t aB = smem_u32(smem + buf * STAGE_FLOATS);
        const uint32_t bB = aB + A_FLOATS * 4;
        #pragma unroll
        for (int i = 0; i < 2; i++) {
            int lin = tid + i * 512;
            int row = lin >> 3, ch = lin & 7;
            cp_async16(aB + (row * PITCH + ch * 4) * 4,
                       W + (size_t)(bd + row) * GK + k0 + ch * 4);
        }
        #pragma unroll
        for (int i = 0; i < 4; i++) {
            int lin = tid + i * 512;
            int row = lin >> 3, ch = lin & 7;
            cp_async16(bB + (row * PITCH + ch * 4) * 4,
                       g_up + (size_t)(bm + row) * GK + k0 + ch * 4);
        }
        asm volatile("cp.async.commit_group;" ::: "memory");
    };

    float acc[2][8][4];
    #pragma unroll
    for (int i = 0; i < 2; i++)
        #pragma unroll
        for (int j = 0; j < 8; j++)
            #pragma unroll
            for (int k = 0; k < 4; k++) acc[i][j][k] = 0.0f;

    load_stage(0, 0);
    load_stage(1, 1);

    for (int c = 0; c < NCH; c++) {
        const int buf = c % 3;
        if (c == NCH - 1)
            asm volatile("cp.async.wait_group 0;" ::: "memory");
        else
            asm volatile("cp.async.wait_group 1;" ::: "memory");
        __syncthreads();

        const float* a_base = smem + buf * STAGE_FLOATS;
        const float* b_base = a_base + A_FLOATS;
        #pragma unroll
        for (int kk = 0; kk < 4; kk++) {
            uint32_t a[2][4];
            #pragma unroll
            for (int mt = 0; mt < 2; mt++) {
                int r = wm + mt * 16 + g;
                const float* ap = a_base + r * PITCH + kk * 8 + th;
                a[mt][0] = __float_as_uint(ap[0]);
                a[mt][1] = __float_as_uint(ap[8 * PITCH]);
                a[mt][2] = __float_as_uint(ap[4]);
                a[mt][3] = __float_as_uint(ap[8 * PITCH + 4]);
            }
            #pragma unroll
            for (int nt = 0; nt < 8; nt++) {
                const float* bp = b_base + (wn + nt * 8 + g) * PITCH + kk * 8 + th;
                uint32_t b0 = __float_as_uint(bp[0]);
                uint32_t b1 = __float_as_uint(bp[4]);
                mma_tf32(acc[0][nt], a[0], b0, b1);
                mma_tf32(acc[1][nt], a[1], b0, b1);
            }
        }
        // 3-stage: buffer (c+2)%3 == (c-1)%3 was fully consumed before the
        // __syncthreads above -> safe to overwrite without a second barrier.
        if (c + 2 < NCH) load_stage(c + 2, (c + 2) % 3);
    }

    #pragma unroll
    for (int mt = 0; mt < 2; mt++) {
        #pragma unroll
        for (int e2 = 0; e2 < 2; e2++) {
            int r = bd + wm + mt * 16 + g + e2 * 8;
            float bv = bias[r];
            float* orow = out + (size_t)r * GM + bm;
            #pragma unroll
            for (int nt = 0; nt < 8; nt++) {
                int c0 = wn + nt * 8 + 2 * th;
                float2 v;
                v.x = acc[mt][nt][e2 * 2 + 0] + bv;
                v.y = acc[mt][nt][e2 * 2 + 1] + bv;
                if (z == 0) {
                    v.x = softplus_f(v.x) + DT_MIN;
                    v.y = softplus_f(v.y) + DT_MIN;
                }
                *reinterpret_cast<float2*>(orow + c0) = v;
            }
        }
    }
}

// ---------------------------------------------------------------------------
// Scan phase A: per (channel, chunk j<CCH-1) compute P[n] = prod Abar,
// S[n] = chunk-local state (x_start = 0). Thread = one channel, 16 states.
// ---------------------------------------------------------------------------
__global__ void __launch_bounds__(128)
scanA_kernel(const float* __restrict__ a_raw, const float* __restrict__ B_base) {
    const int ch = blockIdx.x * 128 + threadIdx.x;
    const int j  = blockIdx.y;
    const int b = ch >> 11, d = ch & 2047;

    float kA[16], Bb[16], P[16], S[16];
    #pragma unroll
    for (int n = 0; n < 16; n++) {
        kA[n] = -softplus_f(a_raw[d * GN_STATE + n]) * 1.4426950408889634f;
        Bb[n] = B_base[d * GN_STATE + n];
        P[n] = 1.0f;
        S[n] = 0.0f;
    }

    const size_t sbase = (size_t)d * GM + (size_t)b * GL + (size_t)j * TCH;
    const float* __restrict__ pdt = g_proj + sbase;
    const float* __restrict__ pbv = g_proj + PLANE + sbase;
    const float* __restrict__ pu  = g_ut + sbase;

    auto step = [&](float dts, float bs, float us) {
        const float w = dts * bs * us;
        #pragma unroll
        for (int n = 0; n < 16; n++) {
            float Abar = ex2f(dts * kA[n]);
            P[n] *= Abar;
            S[n] = fmaf(Abar, S[n], w * Bb[n]);
        }
    };

    for (int tt = 0; tt < TCH; tt += 4) {
        float4 d4 = *reinterpret_cast<const float4*>(pdt + tt);
        float4 b4 = *reinterpret_cast<const float4*>(pbv + tt);
        float4 u4 = *reinterpret_cast<const float4*>(pu + tt);
        step(d4.x, b4.x, u4.x);
        step(d4.y, b4.y, u4.y);
        step(d4.z, b4.z, u4.z);
        step(d4.w, b4.w, u4.w);
    }

    const int o = (j * NCHAN + ch) * GN_STATE;
    #pragma unroll
    for (int n = 0; n < 16; n++) {
        g_P[o + n] = P[n];
        g_S[o + n] = S[n];
    }
}

// ---------------------------------------------------------------------------
// Scan combine: propagate chunk carries. x0(0)=0; x0(j)=S(j-1)+P(j-1)*x0(j-1)
// ---------------------------------------------------------------------------
__global__ void __launch_bounds__(256)
scanC_kernel() {
    const int id = blockIdx.x * 256 + threadIdx.x;   // 0 .. NCHAN*16-1
    float x = 0.0f;
    g_x0[id] = 0.0f;
    #pragma unroll
    for (int j = 1; j < CCH; j++) {
        const int o = (j - 1) * NCHAN * GN_STATE + id;
        x = g_S[o] + g_P[o] * x;
        g_x0[j * NCHAN * GN_STATE + id] = x;
    }
}

// ---------------------------------------------------------------------------
// Scan phase B: full walk per chunk with known x_start; emits y (+ carry).
// ---------------------------------------------------------------------------
__global__ void __launch_bounds__(128)
scanB_kernel(const float* __restrict__ a_raw, const float* __restrict__ B_base,
             const float* __restrict__ C_base, const float* __restrict__ Dv,
             float* __restrict__ carry, float* __restrict__ y) {
    const int ch = blockIdx.x * 128 + threadIdx.x;
    const int j  = blockIdx.y;
    const int b = ch >> 11, d = ch & 2047;

    float kA[16], Bb[16], Cb[16], x[16];
    #pragma unroll
    for (int n = 0; n < 16; n++) {
        kA[n] = -softplus_f(a_raw[d * GN_STATE + n]) * 1.4426950408889634f;
        Bb[n] = B_base[d * GN_STATE + n];
        Cb[n] = C_base[d * GN_STATE + n];
        x[n]  = g_x0[(j * NCHAN + ch) * GN_STATE + n];
    }
    const float Dd = Dv[d];

    const size_t sbase = (size_t)d * GM + (size_t)b * GL + (size_t)j * TCH;
    const float* __restrict__ pdt = g_proj + sbase;
    const float* __restrict__ pbv = g_proj + PLANE + sbase;
    const float* __restrict__ pcv = g_proj + 2 * PLANE + sbase;
    const float* __restrict__ pu  = g_ut + sbase;
    float* __restrict__ yb = y + ((size_t)b * GL + (size_t)j * TCH) * GD + d;

    auto step = [&](float dts, float bs, float cs, float us, int t) {
        const float w = dts * bs * us;
        float acc = 0.0f;
        #pragma unroll
        for (int n = 0; n < 16; n++) {
            float Abar = ex2f(dts * kA[n]);
            x[n] = fmaf(Abar, x[n], w * Bb[n]);
            acc = fmaf(x[n], Cb[n], acc);
        }
        yb[(size_t)t * GD] = fmaf(cs, acc, Dd * us);
    };

    for (int tt = 0; tt < TCH; tt += 4) {
        float4 d4 = *reinterpret_cast<const float4*>(pdt + tt);
        float4 b4 = *reinterpret_cast<const float4*>(pbv + tt);
        float4 c4 = *reinterpret_cast<const float4*>(pcv + tt);
        float4 u4 = *reinterpret_cast<const float4*>(pu + tt);
        step(d4.x, b4.x, c4.x, u4.x, tt + 0);
        step(d4.y, b4.y, c4.y, u4.y, tt + 1);
        step(d4.z, b4.z, c4.z, u4.z, tt + 2);
        step(d4.w, b4.w, c4.w, u4.w, tt + 3);
    }

    if (j == CCH - 1 && carry != nullptr) {
        #pragma unroll
        for (int n = 0; n < 16; n++)
            carry[((size_t)b * GD + d) * GN_STATE + n] = x[n];
    }
}

// ---------------------------------------------------------------------------
extern "C" void kernel_launch(void* const* d_in, const int* in_sizes, int n_in,
                              void* d_out, int out_size) {
    const float* u      = (const float*)d_in[0];
    const float* Wdt    = (const float*)d_in[1];
    const float* bdt    = (const float*)d_in[2];
    const float* Wb     = (const float*)d_in[3];
    const float* bb     = (const float*)d_in[4];
    const float* Wc     = (const float*)d_in[5];
    const float* bc     = (const float*)d_in[6];
    const float* a_raw  = (const float*)d_in[7];
    const float* B_base = (const float*)d_in[8];
    const float* C_base = (const float*)d_in[9];
    const float* Dv     = (const float*)d_in[10];

    float* out = (float*)d_out;
    const long long y_elems = (long long)GB * GL * GD;
    float* carry = nullptr;
    float* y = out;
    if ((long long)out_size > y_elems) {
        carry = out;
        y = out + ((long long)out_size - y_elems);
    }

    cudaFuncSetAttribute(gemm_tc_kernel,
                         cudaFuncAttributeMaxDynamicSharedMemorySize, GEMM_SMEM);

    dim3 tgrid(GK / 32, GD / 32, 3);
    wtrans_kernel<<<tgrid, dim3(32, 8)>>>(Wdt, Wb, Wc);

    dim3 ugrid(GD / 32, GM / 32);
    uprep_kernel<<<ugrid, dim3(32, 8)>>>(u);

    dim3 ggrid(3 * (GD / 128), GM / 256);   // (48, 64)
    gemm_tc_kernel<<<ggrid, 512, GEMM_SMEM>>>(bdt, bb, bc);

    scanA_kernel<<<dim3(NCHAN / 128, CCH - 1), 128>>>(a_raw, B_base);
    scanC_kernel<<<NCHAN * GN_STATE / 256, 256>>>();
    scanB_kernel<<<dim3(NCHAN / 128, CCH), 128>>>(a_raw, B_base, C_base, Dv,
                                                  carry, y);
}